// round 2
// baseline (speedup 1.0000x reference)
#include <cuda_runtime.h>
#include <cstdint>

#define NN 16384
#define DD 8
#define SS 8192
#define TI 32
#define TJ 256

// -------- scratch (no allocations allowed) --------
__device__ int    g_hist[NN];
__device__ int    g_ucols[SS];       // sorted unique sample values (padded)
__device__ int    g_cnt[SS];         // multiplicities (0 for padding)
__device__ float  g_cntf[SS];        // multiplicities as float
__device__ float  g_z[SS * DD];      // gathered z (unique, sorted)
__device__ float  g_sq[SS];          // |z|^2
__device__ int    g_meta[4];         // U, UPAD, n_tj, n_tiles
__device__ double g_acc;

// -------- packed f32x2 helpers --------
__device__ __forceinline__ unsigned long long pk2(float lo, float hi) {
    unsigned long long r;
    asm("mov.b64 %0, {%1, %2};" : "=l"(r) : "f"(lo), "f"(hi));
    return r;
}
__device__ __forceinline__ void upk2(unsigned long long v, float& lo, float& hi) {
    asm("mov.b64 {%0, %1}, %2;" : "=f"(lo), "=f"(hi) : "l"(v));
}
__device__ __forceinline__ unsigned long long fma2(unsigned long long a,
                                                   unsigned long long b,
                                                   unsigned long long c) {
    unsigned long long d;
    asm("fma.rn.f32x2 %0, %1, %2, %3;" : "=l"(d) : "l"(a), "l"(b), "l"(c));
    return d;
}
__device__ __forceinline__ unsigned long long add2(unsigned long long a,
                                                   unsigned long long b) {
    unsigned long long d;
    asm("add.rn.f32x2 %0, %1, %2;" : "=l"(d) : "l"(a), "l"(b));
    return d;
}
__device__ __forceinline__ float fsqrt_ap(float x) {
    float r; asm("sqrt.approx.f32 %0, %1;" : "=f"(r) : "f"(x)); return r;
}
__device__ __forceinline__ float frcp_ap(float x) {
    float r; asm("rcp.approx.f32 %0, %1;" : "=f"(r) : "f"(x)); return r;
}

// -------- 1) zero hist + acc --------
__global__ void k_init() {
    int t = blockIdx.x * blockDim.x + threadIdx.x;
    if (t < NN) g_hist[t] = 0;
    if (t == 0) g_acc = 0.0;
}

// -------- 2) histogram of sample_idx --------
__global__ void k_hist(const int* __restrict__ idx) {
    int t = blockIdx.x * blockDim.x + threadIdx.x;
    if (t < SS) atomicAdd(&g_hist[idx[t]], 1);
}

// -------- 3) one block: scan nonzero bins, emit unique+count, pad,
//            gather z/|z|^2, and add the diagonal correction term --------
__global__ void __launch_bounds__(1024) k_prep(const float* __restrict__ latent,
                                               const float* __restrict__ rel) {
    __shared__ int scn[1024];
    const int tid  = threadIdx.x;
    const int base = tid * 16;

    int cz = 0;
#pragma unroll
    for (int k = 0; k < 16; k++) cz += (g_hist[base + k] > 0);
    scn[tid] = cz;
    __syncthreads();
    // Hillis-Steele inclusive scan over 1024
    for (int off = 1; off < 1024; off <<= 1) {
        int v = (tid >= off) ? scn[tid - off] : 0;
        __syncthreads();
        scn[tid] += v;
        __syncthreads();
    }
    int upos = (tid > 0) ? scn[tid - 1] : 0;
#pragma unroll
    for (int k = 0; k < 16; k++) {
        int c = g_hist[base + k];
        if (c > 0) { g_ucols[upos] = base + k; g_cnt[upos] = c; upos++; }
    }
    const int U    = scn[1023];
    const int UPAD = (U + 255) & ~255;
    // pad with valid index, zero count
    for (int t = U + tid; t < UPAD; t += 1024) {
        g_ucols[t] = NN - 1;
        g_cnt[t]   = 0;
    }
    if (tid == 0) {
        g_meta[0] = U;
        g_meta[1] = UPAD;
        g_meta[2] = UPAD / TJ;
        g_meta[3] = (UPAD / TI) * (UPAD / TJ);
    }
    __syncthreads();

    // gather + diagonal correction
    double dsum = 0.0;
    for (int t = tid; t < UPAD; t += 1024) {
        int v = g_ucols[t];
        float4 a = *reinterpret_cast<const float4*>(latent + (size_t)v * DD);
        float4 b = *reinterpret_cast<const float4*>(latent + (size_t)v * DD + 4);
        float sq = a.x * a.x + a.y * a.y + a.z * a.z + a.w * a.w
                 + b.x * b.x + b.y * b.y + b.z * b.z + b.w * b.w;
        *reinterpret_cast<float4*>(g_z + (size_t)t * DD)     = a;
        *reinterpret_cast<float4*>(g_z + (size_t)t * DD + 4) = b;
        g_sq[t]   = sq;
        int c = g_cnt[t];
        g_cntf[t] = (float)c;
        if (c > 0) {
            float r = __ldg(rel + (size_t)v * NN + v);
            // i==j terms: den is 5 instead of rel_uu:  c*(r^2/5 - r)
            dsum += (double)c * ((double)r * (double)r / 5.0 - (double)r);
        }
    }
#pragma unroll
    for (int o = 16; o > 0; o >>= 1)
        dsum += __shfl_down_sync(0xFFFFFFFFu, dsum, o);
    if ((tid & 31) == 0) atomicAdd(&g_acc, dsum);
}

// -------- 4) main: unique-pair tiles, weighted by c_i*c_j --------
__global__ void __launch_bounds__(TJ) k_main(const float* __restrict__ rel) {
    const int n_tiles = g_meta[3];
    if ((int)blockIdx.x >= n_tiles) return;
    const int n_tj = g_meta[2];
    const int ti = blockIdx.x / n_tj;
    const int tj = blockIdx.x - ti * n_tj;
    const int iBase = ti * TI;
    const int jBase = tj * TJ;

    __shared__ float4 zi4[TI / 2][DD / 2];   // packed (i0,i1) pairs per dim
    __shared__ float2 sqi[TI / 2];
    __shared__ float2 cip[TI / 2];
    __shared__ int    srow[TI];
    __shared__ float  red[8];

    const int tid = threadIdx.x;
    if (tid < 128) {
        int p = tid >> 3, d = tid & 7;
        int i0 = iBase + 2 * p;
        float2 pr = make_float2(g_z[(size_t)i0 * DD + d],
                                g_z[(size_t)(i0 + 1) * DD + d]);
        reinterpret_cast<float2*>(zi4)[p * DD + d] = pr;
    } else if (tid < 160) {
        int k = tid - 128;
        srow[k] = g_ucols[iBase + k];
    } else if (tid < 176) {
        int p = tid - 160;
        sqi[p] = make_float2(g_sq[iBase + 2 * p], g_sq[iBase + 2 * p + 1]);
    } else if (tid < 192) {
        int p = tid - 176;
        cip[p] = make_float2(g_cntf[iBase + 2 * p], g_cntf[iBase + 2 * p + 1]);
    }
    __syncthreads();

    const int j   = jBase + tid;
    const int col = g_ucols[j];
    const float cj = g_cntf[j];
    float4 zj0 = *reinterpret_cast<const float4*>(g_z + (size_t)j * DD);
    float4 zj1 = *reinterpret_cast<const float4*>(g_z + (size_t)j * DD + 4);
    const float sqj = g_sq[j];

    unsigned long long zm[8];
    zm[0] = pk2(-2.f * zj0.x, -2.f * zj0.x);
    zm[1] = pk2(-2.f * zj0.y, -2.f * zj0.y);
    zm[2] = pk2(-2.f * zj0.z, -2.f * zj0.z);
    zm[3] = pk2(-2.f * zj0.w, -2.f * zj0.w);
    zm[4] = pk2(-2.f * zj1.x, -2.f * zj1.x);
    zm[5] = pk2(-2.f * zj1.y, -2.f * zj1.y);
    zm[6] = pk2(-2.f * zj1.z, -2.f * zj1.z);
    zm[7] = pk2(-2.f * zj1.w, -2.f * zj1.w);
    const unsigned long long sqj2 = pk2(sqj, sqj);

    // preload all 32 rel values: maximize MLP
    const float* relc = rel + col;
    float rv[TI];
#pragma unroll
    for (int k = 0; k < TI; k++)
        rv[k] = __ldg(relc + ((size_t)srow[k] << 14));

    float acc = 0.f;
#pragma unroll
    for (int p = 0; p < TI / 2; p++) {
        const ulonglong2* zp = reinterpret_cast<const ulonglong2*>(&zi4[p][0]);
        ulonglong2 e0 = zp[0];
        ulonglong2 e1 = zp[1];

        unsigned long long d2 =
            add2(*reinterpret_cast<const unsigned long long*>(&sqi[p]), sqj2);
        d2 = fma2(e0.x, zm[0], d2);
        d2 = fma2(e0.y, zm[1], d2);
        d2 = fma2(e1.x, zm[2], d2);
        d2 = fma2(e1.y, zm[3], d2);
        ulonglong2 e2 = zp[2];
        ulonglong2 e3 = zp[3];
        d2 = fma2(e2.x, zm[4], d2);
        d2 = fma2(e2.y, zm[5], d2);
        d2 = fma2(e3.x, zm[6], d2);
        d2 = fma2(e3.y, zm[7], d2);

        float d2a, d2b;
        upk2(d2, d2a, d2b);
        float2 ci = cip[p];
        {
            float r  = rv[2 * p];
            float dv = fsqrt_ap(fmaxf(d2a, 0.f));
            float t  = dv - r;
            float term = (t * t) * frcp_ap(r);
            acc = fmaf(ci.x, term, acc);
        }
        {
            float r  = rv[2 * p + 1];
            float dv = fsqrt_ap(fmaxf(d2b, 0.f));
            float t  = dv - r;
            float term = (t * t) * frcp_ap(r);
            acc = fmaf(ci.y, term, acc);
        }
    }
    acc *= cj;

#pragma unroll
    for (int o = 16; o > 0; o >>= 1)
        acc += __shfl_down_sync(0xFFFFFFFFu, acc, o);
    if ((tid & 31) == 0) red[tid >> 5] = acc;
    __syncthreads();
    if (tid < 8) {
        float v = red[tid];
#pragma unroll
        for (int o = 4; o > 0; o >>= 1)
            v += __shfl_down_sync(0xFFu, v, o);
        if (tid == 0) atomicAdd(&g_acc, (double)v);
    }
}

// -------- 5) finalize --------
__global__ void k_final(float* __restrict__ out) {
    out[0] = (float)sqrt(g_acc);
}

extern "C" void kernel_launch(void* const* d_in, const int* in_sizes, int n_in,
                              void* d_out, int out_size) {
    const float* latent = (const float*)d_in[0];   // [N, D] fp32
    const float* relmat = (const float*)d_in[1];   // [N, N] fp32
    const int*   sidx   = (const int*)d_in[2];     // [S]   int32
    float* out = (float*)d_out;
    (void)in_sizes; (void)n_in; (void)out_size;

    k_init<<<NN / 256, 256>>>();
    k_hist<<<SS / 256, 256>>>(sidx);
    k_prep<<<1, 1024>>>(latent, relmat);
    k_main<<<SS, TJ>>>(relmat);   // 8192 blocks; blocks >= n_tiles exit
    k_final<<<1, 1>>>(out);
}

// round 3
// speedup vs baseline: 1.5530x; 1.5530x over previous
#include <cuda_runtime.h>
#include <cstdint>

#define NN 16384
#define DD 8
#define SS 8192
#define TI 64          // i-rows per block (two halves of 32)
#define TJ 256         // j-cols per block (= blockDim.x)

// -------- scratch (no allocations; all zero-init at load) --------
__device__ int    g_hist[NN];        // zeroed by k_emit each run (self-restoring)
__device__ int    g_bsum[128];
__device__ int    g_boff[128];
__device__ int    g_ucols[SS];       // sorted unique sample values (padded)
__device__ float  g_cntf[SS];        // multiplicities as float (0 for padding)
__device__ float  g_z[SS * DD];      // gathered z (unique, sorted)
__device__ float  g_sq[SS];          // |z|^2
__device__ int    g_meta[4];         // U, UPAD, n_tj, n_tiles
__device__ double g_acc;             // reset by k_final each run

// -------- packed f32x2 helpers --------
__device__ __forceinline__ unsigned long long pk2(float lo, float hi) {
    unsigned long long r;
    asm("mov.b64 %0, {%1, %2};" : "=l"(r) : "f"(lo), "f"(hi));
    return r;
}
__device__ __forceinline__ void upk2(unsigned long long v, float& lo, float& hi) {
    asm("mov.b64 {%0, %1}, %2;" : "=f"(lo), "=f"(hi) : "l"(v));
}
__device__ __forceinline__ unsigned long long fma2(unsigned long long a,
                                                   unsigned long long b,
                                                   unsigned long long c) {
    unsigned long long d;
    asm("fma.rn.f32x2 %0, %1, %2, %3;" : "=l"(d) : "l"(a), "l"(b), "l"(c));
    return d;
}
__device__ __forceinline__ unsigned long long add2(unsigned long long a,
                                                   unsigned long long b) {
    unsigned long long d;
    asm("add.rn.f32x2 %0, %1, %2;" : "=l"(d) : "l"(a), "l"(b));
    return d;
}
__device__ __forceinline__ float fsqrt_ap(float x) {
    float r; asm("sqrt.approx.f32 %0, %1;" : "=f"(r) : "f"(x)); return r;
}
__device__ __forceinline__ float frcp_ap(float x) {
    float r; asm("rcp.approx.f32 %0, %1;" : "=f"(r) : "f"(x)); return r;
}

// -------- 1) histogram (g_hist is zero: static init / re-zeroed by k_emit) --------
__global__ void k_hist(const int* __restrict__ idx) {
    int t = blockIdx.x * blockDim.x + threadIdx.x;
    if (t < SS) atomicAdd(&g_hist[idx[t]], 1);
}

// -------- 2) per-chunk nonzero counts (128 blocks x 128 bins) --------
__global__ void __launch_bounds__(128) k_scan1() {
    __shared__ int ws[4];
    int v = blockIdx.x * 128 + threadIdx.x;
    int f = (g_hist[v] > 0) ? 1 : 0;
#pragma unroll
    for (int o = 16; o > 0; o >>= 1) f += __shfl_down_sync(0xFFFFFFFFu, f, o);
    if ((threadIdx.x & 31) == 0) ws[threadIdx.x >> 5] = f;
    __syncthreads();
    if (threadIdx.x == 0)
        g_bsum[blockIdx.x] = ws[0] + ws[1] + ws[2] + ws[3];
}

// -------- 3) scan 128 chunk sums, write meta, fill padding --------
__global__ void __launch_bounds__(128) k_scan2(const float* __restrict__ latent) {
    __shared__ int scn[128];
    const int tid = threadIdx.x;
    scn[tid] = g_bsum[tid];
    __syncthreads();
    for (int off = 1; off < 128; off <<= 1) {
        int v = (tid >= off) ? scn[tid - off] : 0;
        __syncthreads();
        scn[tid] += v;
        __syncthreads();
    }
    g_boff[tid] = (tid > 0) ? scn[tid - 1] : 0;   // exclusive
    const int U    = scn[127];
    const int UPAD = (U + 255) & ~255;
    if (tid == 0) {
        g_meta[0] = U;
        g_meta[1] = UPAD;
        g_meta[2] = UPAD / TJ;
        g_meta[3] = (UPAD / TI) * (UPAD / TJ);
    }
    // fill padding entries [U, UPAD): valid index, zero weight
    for (int t = U + tid; t < UPAD; t += 128) {
        g_ucols[t] = NN - 1;
        g_cntf[t]  = 0.f;
        float4 a = *reinterpret_cast<const float4*>(latent + (size_t)(NN - 1) * DD);
        float4 b = *reinterpret_cast<const float4*>(latent + (size_t)(NN - 1) * DD + 4);
        *reinterpret_cast<float4*>(g_z + (size_t)t * DD)     = a;
        *reinterpret_cast<float4*>(g_z + (size_t)t * DD + 4) = b;
        g_sq[t] = a.x * a.x + a.y * a.y + a.z * a.z + a.w * a.w
                + b.x * b.x + b.y * b.y + b.z * b.z + b.w * b.w;
    }
}

// -------- 4) emit unique+count, gather z, diag correction, re-zero hist --------
__global__ void __launch_bounds__(128) k_emit(const float* __restrict__ latent,
                                              const float* __restrict__ rel) {
    __shared__ int wbase[4];
    __shared__ double dred[4];
    const int tid  = threadIdx.x;
    const int lane = tid & 31;
    const int w    = tid >> 5;
    const int v    = blockIdx.x * 128 + tid;

    const int c = g_hist[v];
    g_hist[v] = 0;                       // restore for next replay
    const bool flag = (c > 0);

    unsigned mask = __ballot_sync(0xFFFFFFFFu, flag);
    int excl = __popc(mask & ((1u << lane) - 1u));
    if (lane == 0) wbase[w] = __popc(mask);
    __syncthreads();
    if (tid == 0) {
        int s = 0;
#pragma unroll
        for (int k = 0; k < 4; k++) { int t = wbase[k]; wbase[k] = s; s += t; }
    }
    __syncthreads();

    double dsum = 0.0;
    if (flag) {
        int pos = g_boff[blockIdx.x] + wbase[w] + excl;
        g_ucols[pos] = v;
        g_cntf[pos]  = (float)c;
        float4 a = *reinterpret_cast<const float4*>(latent + (size_t)v * DD);
        float4 b = *reinterpret_cast<const float4*>(latent + (size_t)v * DD + 4);
        *reinterpret_cast<float4*>(g_z + (size_t)pos * DD)     = a;
        *reinterpret_cast<float4*>(g_z + (size_t)pos * DD + 4) = b;
        g_sq[pos] = a.x * a.x + a.y * a.y + a.z * a.z + a.w * a.w
                  + b.x * b.x + b.y * b.y + b.z * b.z + b.w * b.w;
        // diagonal re-pricing: den 5 instead of rel_vv (dist=0 on diag)
        float r = __ldg(rel + (size_t)v * NN + v);
        dsum = (double)c * ((double)r * (double)r / 5.0 - (double)r);
    }
#pragma unroll
    for (int o = 16; o > 0; o >>= 1)
        dsum += __shfl_down_sync(0xFFFFFFFFu, dsum, o);
    if (lane == 0) dred[w] = dsum;
    __syncthreads();
    if (tid == 0)
        atomicAdd(&g_acc, dred[0] + dred[1] + dred[2] + dred[3]);
}

// -------- 5) main: 64 x 256 unique-pair tiles, weighted by c_i*c_j --------
__global__ void __launch_bounds__(TJ) k_main(const float* __restrict__ rel) {
    const int n_tiles = g_meta[3];
    if ((int)blockIdx.x >= n_tiles) return;
    const int n_tj = g_meta[2];
    const int ti = blockIdx.x / n_tj;
    const int tj = blockIdx.x - ti * n_tj;
    const int iBase = ti * TI;
    const int jBase = tj * TJ;

    __shared__ float4 zi4[TI / 2][DD / 2];   // 32 packed (i0,i1) pairs x 4 f2-dims
    __shared__ float2 sqi[TI / 2];
    __shared__ float2 cip[TI / 2];
    __shared__ int    srow[TI];
    __shared__ float  red[8];

    const int tid = threadIdx.x;
    {   // 256 threads fill exactly the 256 float2 slots of zi4
        int p = tid >> 3, d = tid & 7;
        int i0 = iBase + 2 * p;
        float2 pr = make_float2(g_z[(size_t)i0 * DD + d],
                                g_z[(size_t)(i0 + 1) * DD + d]);
        reinterpret_cast<float2*>(zi4)[p * DD + d] = pr;
    }
    if (tid < TI) srow[tid] = g_ucols[iBase + tid];
    else if (tid < TI + 32) {
        int p = tid - TI;
        sqi[p] = make_float2(g_sq[iBase + 2 * p], g_sq[iBase + 2 * p + 1]);
    } else if (tid < TI + 64) {
        int p = tid - TI - 32;
        cip[p] = make_float2(g_cntf[iBase + 2 * p], g_cntf[iBase + 2 * p + 1]);
    }
    __syncthreads();

    const int j   = jBase + tid;
    const int col = g_ucols[j];
    const float cj = g_cntf[j];
    float4 zj0 = *reinterpret_cast<const float4*>(g_z + (size_t)j * DD);
    float4 zj1 = *reinterpret_cast<const float4*>(g_z + (size_t)j * DD + 4);
    const float sqj = g_sq[j];

    unsigned long long zm[8];
    zm[0] = pk2(-2.f * zj0.x, -2.f * zj0.x);
    zm[1] = pk2(-2.f * zj0.y, -2.f * zj0.y);
    zm[2] = pk2(-2.f * zj0.z, -2.f * zj0.z);
    zm[3] = pk2(-2.f * zj0.w, -2.f * zj0.w);
    zm[4] = pk2(-2.f * zj1.x, -2.f * zj1.x);
    zm[5] = pk2(-2.f * zj1.y, -2.f * zj1.y);
    zm[6] = pk2(-2.f * zj1.z, -2.f * zj1.z);
    zm[7] = pk2(-2.f * zj1.w, -2.f * zj1.w);
    const unsigned long long sqj2 = pk2(sqj, sqj);
    const float* relc = rel + col;

    float acc0 = 0.f, acc1 = 0.f;
#pragma unroll
    for (int h = 0; h < 2; h++) {
        // preload this half's 32 rel values (deep MLP)
        float rv[32];
#pragma unroll
        for (int k = 0; k < 32; k++)
            rv[k] = __ldg(relc + ((size_t)srow[h * 32 + k] << 14));

#pragma unroll
        for (int pp = 0; pp < 16; pp++) {
            const int p = h * 16 + pp;
            const ulonglong2* zp = reinterpret_cast<const ulonglong2*>(&zi4[p][0]);
            ulonglong2 e0 = zp[0];
            ulonglong2 e1 = zp[1];
            unsigned long long d2 =
                add2(*reinterpret_cast<const unsigned long long*>(&sqi[p]), sqj2);
            d2 = fma2(e0.x, zm[0], d2);
            d2 = fma2(e0.y, zm[1], d2);
            d2 = fma2(e1.x, zm[2], d2);
            d2 = fma2(e1.y, zm[3], d2);
            ulonglong2 e2 = zp[2];
            ulonglong2 e3 = zp[3];
            d2 = fma2(e2.x, zm[4], d2);
            d2 = fma2(e2.y, zm[5], d2);
            d2 = fma2(e3.x, zm[6], d2);
            d2 = fma2(e3.y, zm[7], d2);

            float d2a, d2b;
            upk2(d2, d2a, d2b);
            float2 ci = cip[p];
            {
                float r  = rv[2 * pp];
                float dv = fsqrt_ap(fmaxf(d2a, 0.f));
                float t  = dv - r;
                acc0 = fmaf(ci.x, (t * t) * frcp_ap(r), acc0);
            }
            {
                float r  = rv[2 * pp + 1];
                float dv = fsqrt_ap(fmaxf(d2b, 0.f));
                float t  = dv - r;
                acc1 = fmaf(ci.y, (t * t) * frcp_ap(r), acc1);
            }
        }
    }
    float acc = (acc0 + acc1) * cj;

#pragma unroll
    for (int o = 16; o > 0; o >>= 1)
        acc += __shfl_down_sync(0xFFFFFFFFu, acc, o);
    if ((tid & 31) == 0) red[tid >> 5] = acc;
    __syncthreads();
    if (tid < 8) {
        float v = red[tid];
#pragma unroll
        for (int o = 4; o > 0; o >>= 1)
            v += __shfl_down_sync(0xFFu, v, o);
        if (tid == 0) atomicAdd(&g_acc, (double)v);
    }
}

// -------- 6) finalize + restore accumulator --------
__global__ void k_final(float* __restrict__ out) {
    out[0] = (float)sqrt(g_acc);
    g_acc = 0.0;                       // restore for next replay
}

extern "C" void kernel_launch(void* const* d_in, const int* in_sizes, int n_in,
                              void* d_out, int out_size) {
    const float* latent = (const float*)d_in[0];   // [N, D] fp32
    const float* relmat = (const float*)d_in[1];   // [N, N] fp32
    const int*   sidx   = (const int*)d_in[2];     // [S]   int32
    float* out = (float*)d_out;
    (void)in_sizes; (void)n_in; (void)out_size;

    k_hist<<<SS / 256, 256>>>(sidx);
    k_scan1<<<128, 128>>>();
    k_scan2<<<1, 128>>>(latent);
    k_emit<<<128, 128>>>(latent, relmat);

    k_main<<<(SS / TI) * (SS / TJ), TJ>>>(relmat);  // 4096 max; extras exit
    k_final<<<1, 1>>>(out);
}

// round 4
// speedup vs baseline: 1.5873x; 1.0221x over previous
#include <cuda_runtime.h>
#include <cstdint>

#define NN 16384
#define DD 8
#define SS 8192
#define TI 64          // i-rows per block
#define TJ 256         // j-cols per block (= blockDim.x)

// -------- scratch (no allocations; zero-init at load; self-restoring) --------
__device__ int    g_hist[NN];        // re-zeroed by k_emit each run
__device__ int    g_bsum[128];
__device__ int    g_ucols[SS];       // sorted unique sample values (padded)
__device__ float  g_cntf[SS];        // multiplicities as float (0 for padding)
__device__ float  g_z[SS * DD];      // gathered z (unique, sorted)
__device__ float  g_sq[SS];          // |z|^2
__device__ int    g_meta[4];         // U, UPAD, n_tj, n_tiles
__device__ double g_acc;             // reset by k_final each run

// -------- packed f32x2 helpers --------
__device__ __forceinline__ unsigned long long pk2(float lo, float hi) {
    unsigned long long r;
    asm("mov.b64 %0, {%1, %2};" : "=l"(r) : "f"(lo), "f"(hi));
    return r;
}
__device__ __forceinline__ void upk2(unsigned long long v, float& lo, float& hi) {
    asm("mov.b64 {%0, %1}, %2;" : "=f"(lo), "=f"(hi) : "l"(v));
}
__device__ __forceinline__ unsigned long long fma2(unsigned long long a,
                                                   unsigned long long b,
                                                   unsigned long long c) {
    unsigned long long d;
    asm("fma.rn.f32x2 %0, %1, %2, %3;" : "=l"(d) : "l"(a), "l"(b), "l"(c));
    return d;
}
__device__ __forceinline__ unsigned long long add2(unsigned long long a,
                                                   unsigned long long b) {
    unsigned long long d;
    asm("add.rn.f32x2 %0, %1, %2;" : "=l"(d) : "l"(a), "l"(b));
    return d;
}
__device__ __forceinline__ float fsqrt_ap(float x) {
    float r; asm("sqrt.approx.f32 %0, %1;" : "=f"(r) : "f"(x)); return r;
}
__device__ __forceinline__ float frcp_ap(float x) {
    float r; asm("rcp.approx.f32 %0, %1;" : "=f"(r) : "f"(x)); return r;
}

// -------- 1) histogram + per-sample diagonal correction --------
// diag term: sum over SAMPLES s of (r_ss^2/5 - r_ss), r_ss = rel[idx_s, idx_s]
__global__ void __launch_bounds__(256) k_hist(const int* __restrict__ idx,
                                              const float* __restrict__ rel) {
    __shared__ double dred[8];
    int t = blockIdx.x * blockDim.x + threadIdx.x;
    int v = idx[t];
    atomicAdd(&g_hist[v], 1);
    float r = __ldg(rel + (size_t)v * NN + v);
    double dsum = (double)r * (double)r / 5.0 - (double)r;
#pragma unroll
    for (int o = 16; o > 0; o >>= 1)
        dsum += __shfl_down_sync(0xFFFFFFFFu, dsum, o);
    if ((threadIdx.x & 31) == 0) dred[threadIdx.x >> 5] = dsum;
    __syncthreads();
    if (threadIdx.x == 0) {
        double s = 0.0;
#pragma unroll
        for (int k = 0; k < 8; k++) s += dred[k];
        atomicAdd(&g_acc, s);
    }
}

// -------- 2) per-chunk nonzero counts (128 blocks x 128 bins) --------
__global__ void __launch_bounds__(128) k_scan1() {
    __shared__ int ws[4];
    int v = blockIdx.x * 128 + threadIdx.x;
    int f = (g_hist[v] > 0) ? 1 : 0;
#pragma unroll
    for (int o = 16; o > 0; o >>= 1) f += __shfl_down_sync(0xFFFFFFFFu, f, o);
    if ((threadIdx.x & 31) == 0) ws[threadIdx.x >> 5] = f;
    __syncthreads();
    if (threadIdx.x == 0)
        g_bsum[blockIdx.x] = ws[0] + ws[1] + ws[2] + ws[3];
}

// -------- 3) emit unique+count, gather z, meta+padding (block 127), re-zero hist --------
__global__ void __launch_bounds__(128) k_emit(const float* __restrict__ latent) {
    __shared__ int wbase[4];
    __shared__ int s_pre[4], s_tot[4];
    __shared__ int blkoff, total;
    const int tid  = threadIdx.x;
    const int lane = tid & 31;
    const int w    = tid >> 5;
    const int bid  = blockIdx.x;

    // block offset = sum of g_bsum[b] for b < bid; total = sum of all
    {
        int bs  = g_bsum[tid];
        int pre = (tid < bid) ? bs : 0;
#pragma unroll
        for (int o = 16; o > 0; o >>= 1) {
            pre += __shfl_down_sync(0xFFFFFFFFu, pre, o);
            bs  += __shfl_down_sync(0xFFFFFFFFu, bs, o);
        }
        if (lane == 0) { s_pre[w] = pre; s_tot[w] = bs; }
        __syncthreads();
        if (tid == 0) {
            blkoff = s_pre[0] + s_pre[1] + s_pre[2] + s_pre[3];
            total  = s_tot[0] + s_tot[1] + s_tot[2] + s_tot[3];
        }
    }

    const int v = bid * 128 + tid;
    const int c = g_hist[v];
    g_hist[v] = 0;                       // restore for next replay
    const bool flag = (c > 0);

    unsigned mask = __ballot_sync(0xFFFFFFFFu, flag);
    int excl = __popc(mask & ((1u << lane) - 1u));
    if (lane == 0) wbase[w] = __popc(mask);
    __syncthreads();
    if (tid == 0) {
        int s = 0;
#pragma unroll
        for (int k = 0; k < 4; k++) { int t = wbase[k]; wbase[k] = s; s += t; }
    }
    __syncthreads();

    if (flag) {
        int pos = blkoff + wbase[w] + excl;
        g_ucols[pos] = v;
        g_cntf[pos]  = (float)c;
        float4 a = *reinterpret_cast<const float4*>(latent + (size_t)v * DD);
        float4 b = *reinterpret_cast<const float4*>(latent + (size_t)v * DD + 4);
        *reinterpret_cast<float4*>(g_z + (size_t)pos * DD)     = a;
        *reinterpret_cast<float4*>(g_z + (size_t)pos * DD + 4) = b;
        g_sq[pos] = a.x * a.x + a.y * a.y + a.z * a.z + a.w * a.w
                  + b.x * b.x + b.y * b.y + b.z * b.z + b.w * b.w;
    }

    // block 127: write meta + fill padding [U, UPAD)
    if (bid == 127) {
        const int U    = total;
        const int UPAD = (U + 255) & ~255;
        if (tid == 0) {
            g_meta[0] = U;
            g_meta[1] = UPAD;
            g_meta[2] = UPAD / TJ;
            g_meta[3] = (UPAD / TI) * (UPAD / TJ);
        }
        float4 a = *reinterpret_cast<const float4*>(latent + (size_t)(NN - 1) * DD);
        float4 b = *reinterpret_cast<const float4*>(latent + (size_t)(NN - 1) * DD + 4);
        float sq = a.x * a.x + a.y * a.y + a.z * a.z + a.w * a.w
                 + b.x * b.x + b.y * b.y + b.z * b.z + b.w * b.w;
        for (int t = U + tid; t < UPAD; t += 128) {
            g_ucols[t] = NN - 1;
            g_cntf[t]  = 0.f;
            *reinterpret_cast<float4*>(g_z + (size_t)t * DD)     = a;
            *reinterpret_cast<float4*>(g_z + (size_t)t * DD + 4) = b;
            g_sq[t] = sq;
        }
    }
}

// -------- 4) main: 64 x 256 unique-pair tiles, c_i*c_j weighted,
//            double-buffered rel preload (4 chunks of 16) --------
__global__ void __launch_bounds__(TJ) k_main(const float* __restrict__ rel) {
    const int n_tiles = g_meta[3];
    if ((int)blockIdx.x >= n_tiles) return;
    const int n_tj = g_meta[2];
    const int ti = blockIdx.x / n_tj;
    const int tj = blockIdx.x - ti * n_tj;
    const int iBase = ti * TI;
    const int jBase = tj * TJ;

    __shared__ float4 zi4[TI / 2][DD / 2];   // packed (i0,i1) pairs x 4 f2-dims
    __shared__ float2 sqi[TI / 2];
    __shared__ float2 cip[TI / 2];
    __shared__ int    srow[TI];              // pre-shifted row offsets (floats)
    __shared__ float  red[8];

    const int tid = threadIdx.x;
    {   // 256 threads fill exactly the 256 float2 slots of zi4
        int p = tid >> 3, d = tid & 7;
        int i0 = iBase + 2 * p;
        float2 pr = make_float2(g_z[(size_t)i0 * DD + d],
                                g_z[(size_t)(i0 + 1) * DD + d]);
        reinterpret_cast<float2*>(zi4)[p * DD + d] = pr;
    }
    if (tid < TI) srow[tid] = g_ucols[iBase + tid] << 14;   // *NN
    else if (tid < TI + 32) {
        int p = tid - TI;
        sqi[p] = make_float2(g_sq[iBase + 2 * p], g_sq[iBase + 2 * p + 1]);
    } else if (tid < TI + 64) {
        int p = tid - TI - 32;
        cip[p] = make_float2(g_cntf[iBase + 2 * p], g_cntf[iBase + 2 * p + 1]);
    }
    __syncthreads();

    const int j   = jBase + tid;
    const int col = g_ucols[j];
    const float cj = g_cntf[j];
    const float* relc = rel + col;

    // first rel chunk in flight before zj setup
    float rv[2][16];
#pragma unroll
    for (int k = 0; k < 16; k++)
        rv[0][k] = __ldg(relc + (size_t)srow[k]);

    float4 zj0 = *reinterpret_cast<const float4*>(g_z + (size_t)j * DD);
    float4 zj1 = *reinterpret_cast<const float4*>(g_z + (size_t)j * DD + 4);
    const float sqj = g_sq[j];

    unsigned long long zm[8];
    zm[0] = pk2(-2.f * zj0.x, -2.f * zj0.x);
    zm[1] = pk2(-2.f * zj0.y, -2.f * zj0.y);
    zm[2] = pk2(-2.f * zj0.z, -2.f * zj0.z);
    zm[3] = pk2(-2.f * zj0.w, -2.f * zj0.w);
    zm[4] = pk2(-2.f * zj1.x, -2.f * zj1.x);
    zm[5] = pk2(-2.f * zj1.y, -2.f * zj1.y);
    zm[6] = pk2(-2.f * zj1.z, -2.f * zj1.z);
    zm[7] = pk2(-2.f * zj1.w, -2.f * zj1.w);
    const unsigned long long sqj2 = pk2(sqj, sqj);

    float acc0 = 0.f, acc1 = 0.f;
#pragma unroll
    for (int c = 0; c < 4; c++) {
        const int cur = c & 1;
        if (c < 3) {                         // prefetch next chunk
#pragma unroll
            for (int k = 0; k < 16; k++)
                rv[cur ^ 1][k] = __ldg(relc + (size_t)srow[(c + 1) * 16 + k]);
        }
#pragma unroll
        for (int pp = 0; pp < 8; pp++) {
            const int p = c * 8 + pp;
            const ulonglong2* zp = reinterpret_cast<const ulonglong2*>(&zi4[p][0]);
            ulonglong2 e0 = zp[0];
            ulonglong2 e1 = zp[1];
            unsigned long long d2 =
                add2(*reinterpret_cast<const unsigned long long*>(&sqi[p]), sqj2);
            d2 = fma2(e0.x, zm[0], d2);
            d2 = fma2(e0.y, zm[1], d2);
            d2 = fma2(e1.x, zm[2], d2);
            d2 = fma2(e1.y, zm[3], d2);
            ulonglong2 e2 = zp[2];
            ulonglong2 e3 = zp[3];
            d2 = fma2(e2.x, zm[4], d2);
            d2 = fma2(e2.y, zm[5], d2);
            d2 = fma2(e3.x, zm[6], d2);
            d2 = fma2(e3.y, zm[7], d2);

            float d2a, d2b;
            upk2(d2, d2a, d2b);
            float2 ci = cip[p];
            {
                float r  = rv[cur][2 * pp];
                float dv = fsqrt_ap(fmaxf(d2a, 0.f));
                float t  = dv - r;
                acc0 = fmaf(ci.x, (t * t) * frcp_ap(r), acc0);
            }
            {
                float r  = rv[cur][2 * pp + 1];
                float dv = fsqrt_ap(fmaxf(d2b, 0.f));
                float t  = dv - r;
                acc1 = fmaf(ci.y, (t * t) * frcp_ap(r), acc1);
            }
        }
    }
    float acc = (acc0 + acc1) * cj;

#pragma unroll
    for (int o = 16; o > 0; o >>= 1)
        acc += __shfl_down_sync(0xFFFFFFFFu, acc, o);
    if ((tid & 31) == 0) red[tid >> 5] = acc;
    __syncthreads();
    if (tid < 8) {
        float v = red[tid];
#pragma unroll
        for (int o = 4; o > 0; o >>= 1)
            v += __shfl_down_sync(0xFFu, v, o);
        if (tid == 0) atomicAdd(&g_acc, (double)v);
    }
}

// -------- 5) finalize + restore accumulator --------
__global__ void k_final(float* __restrict__ out) {
    out[0] = (float)sqrt(g_acc);
    g_acc = 0.0;                       // restore for next replay
}

extern "C" void kernel_launch(void* const* d_in, const int* in_sizes, int n_in,
                              void* d_out, int out_size) {
    const float* latent = (const float*)d_in[0];   // [N, D] fp32
    const float* relmat = (const float*)d_in[1];   // [N, N] fp32
    const int*   sidx   = (const int*)d_in[2];     // [S]   int32
    float* out = (float*)d_out;
    (void)in_sizes; (void)n_in; (void)out_size;

    k_hist<<<SS / 256, 256>>>(sidx, relmat);
    k_scan1<<<128, 128>>>();
    k_emit<<<128, 128>>>(latent);
    k_main<<<(SS / TI) * (SS / TJ), TJ>>>(relmat);  // 4th launch -> ncu profiles it
    k_final<<<1, 1>>>(out);
}

// round 5
// speedup vs baseline: 1.6845x; 1.0612x over previous
#include <cuda_runtime.h>
#include <cstdint>

#define NN 16384
#define DD 8
#define SS 8192
#define TI 64          // i-rows per block
#define TJ 256         // j-cols per block (= blockDim.x)

// -------- scratch (no allocations; zero-init at load; self-restoring) --------
__device__ int    g_hist[NN];        // re-zeroed by k_emit each run
__device__ int    g_bsum[128];
__device__ int    g_ucols[SS];       // sorted unique sample values (padded)
__device__ float  g_cntf[SS];        // multiplicities as float (0 for padding)
__device__ float  g_z[SS * DD];      // gathered z (unique, sorted)
__device__ float  g_sq[SS];          // |z|^2
__device__ int    g_meta[4];         // U, UPAD, n_tj, n_tiles
__device__ double g_acc;             // reset by k_final each run

// -------- packed f32x2 helpers --------
__device__ __forceinline__ unsigned long long pk2(float lo, float hi) {
    unsigned long long r;
    asm("mov.b64 %0, {%1, %2};" : "=l"(r) : "f"(lo), "f"(hi));
    return r;
}
__device__ __forceinline__ void upk2(unsigned long long v, float& lo, float& hi) {
    asm("mov.b64 {%0, %1}, %2;" : "=f"(lo), "=f"(hi) : "l"(v));
}
__device__ __forceinline__ unsigned long long fma2(unsigned long long a,
                                                   unsigned long long b,
                                                   unsigned long long c) {
    unsigned long long d;
    asm("fma.rn.f32x2 %0, %1, %2, %3;" : "=l"(d) : "l"(a), "l"(b), "l"(c));
    return d;
}
__device__ __forceinline__ unsigned long long add2(unsigned long long a,
                                                   unsigned long long b) {
    unsigned long long d;
    asm("add.rn.f32x2 %0, %1, %2;" : "=l"(d) : "l"(a), "l"(b));
    return d;
}
__device__ __forceinline__ float fsqrt_ap(float x) {
    float r; asm("sqrt.approx.f32 %0, %1;" : "=f"(r) : "f"(x)); return r;
}
__device__ __forceinline__ float frcp_ap(float x) {
    float r; asm("rcp.approx.f32 %0, %1;" : "=f"(r) : "f"(x)); return r;
}

// -------- 1) histogram + per-sample diagonal correction --------
__global__ void __launch_bounds__(256) k_hist(const int* __restrict__ idx,
                                              const float* __restrict__ rel) {
    __shared__ double dred[8];
    int t = blockIdx.x * blockDim.x + threadIdx.x;
    int v = idx[t];
    atomicAdd(&g_hist[v], 1);
    float r = __ldg(rel + (size_t)v * NN + v);
    double dsum = (double)r * (double)r / 5.0 - (double)r;
#pragma unroll
    for (int o = 16; o > 0; o >>= 1)
        dsum += __shfl_down_sync(0xFFFFFFFFu, dsum, o);
    if ((threadIdx.x & 31) == 0) dred[threadIdx.x >> 5] = dsum;
    __syncthreads();
    if (threadIdx.x == 0) {
        double s = 0.0;
#pragma unroll
        for (int k = 0; k < 8; k++) s += dred[k];
        atomicAdd(&g_acc, s);
    }
}

// -------- 2) per-chunk nonzero counts (128 blocks x 128 bins) --------
__global__ void __launch_bounds__(128) k_scan1() {
    __shared__ int ws[4];
    int v = blockIdx.x * 128 + threadIdx.x;
    int f = (g_hist[v] > 0) ? 1 : 0;
#pragma unroll
    for (int o = 16; o > 0; o >>= 1) f += __shfl_down_sync(0xFFFFFFFFu, f, o);
    if ((threadIdx.x & 31) == 0) ws[threadIdx.x >> 5] = f;
    __syncthreads();
    if (threadIdx.x == 0)
        g_bsum[blockIdx.x] = ws[0] + ws[1] + ws[2] + ws[3];
}

// -------- 3) emit unique+count, gather z, meta+padding, re-zero hist --------
__global__ void __launch_bounds__(128) k_emit(const float* __restrict__ latent) {
    __shared__ int wbase[4];
    __shared__ int s_pre[4], s_tot[4];
    __shared__ int blkoff, total;
    const int tid  = threadIdx.x;
    const int lane = tid & 31;
    const int w    = tid >> 5;
    const int bid  = blockIdx.x;

    {
        int bs  = g_bsum[tid];
        int pre = (tid < bid) ? bs : 0;
#pragma unroll
        for (int o = 16; o > 0; o >>= 1) {
            pre += __shfl_down_sync(0xFFFFFFFFu, pre, o);
            bs  += __shfl_down_sync(0xFFFFFFFFu, bs, o);
        }
        if (lane == 0) { s_pre[w] = pre; s_tot[w] = bs; }
        __syncthreads();
        if (tid == 0) {
            blkoff = s_pre[0] + s_pre[1] + s_pre[2] + s_pre[3];
            total  = s_tot[0] + s_tot[1] + s_tot[2] + s_tot[3];
        }
    }

    const int v = bid * 128 + tid;
    const int c = g_hist[v];
    g_hist[v] = 0;
    const bool flag = (c > 0);

    unsigned mask = __ballot_sync(0xFFFFFFFFu, flag);
    int excl = __popc(mask & ((1u << lane) - 1u));
    if (lane == 0) wbase[w] = __popc(mask);
    __syncthreads();
    if (tid == 0) {
        int s = 0;
#pragma unroll
        for (int k = 0; k < 4; k++) { int t = wbase[k]; wbase[k] = s; s += t; }
    }
    __syncthreads();

    if (flag) {
        int pos = blkoff + wbase[w] + excl;
        g_ucols[pos] = v;
        g_cntf[pos]  = (float)c;
        float4 a = *reinterpret_cast<const float4*>(latent + (size_t)v * DD);
        float4 b = *reinterpret_cast<const float4*>(latent + (size_t)v * DD + 4);
        *reinterpret_cast<float4*>(g_z + (size_t)pos * DD)     = a;
        *reinterpret_cast<float4*>(g_z + (size_t)pos * DD + 4) = b;
        g_sq[pos] = a.x * a.x + a.y * a.y + a.z * a.z + a.w * a.w
                  + b.x * b.x + b.y * b.y + b.z * b.z + b.w * b.w;
    }

    if (bid == 127) {
        const int U    = total;
        const int UPAD = (U + 255) & ~255;
        if (tid == 0) {
            g_meta[0] = U;
            g_meta[1] = UPAD;
            g_meta[2] = UPAD / TJ;
            g_meta[3] = (UPAD / TI) * (UPAD / TJ);
        }
        float4 a = *reinterpret_cast<const float4*>(latent + (size_t)(NN - 1) * DD);
        float4 b = *reinterpret_cast<const float4*>(latent + (size_t)(NN - 1) * DD + 4);
        float sq = a.x * a.x + a.y * a.y + a.z * a.z + a.w * a.w
                 + b.x * b.x + b.y * b.y + b.z * b.z + b.w * b.w;
        for (int t = U + tid; t < UPAD; t += 128) {
            g_ucols[t] = NN - 1;
            g_cntf[t]  = 0.f;
            *reinterpret_cast<float4*>(g_z + (size_t)t * DD)     = a;
            *reinterpret_cast<float4*>(g_z + (size_t)t * DD + 4) = b;
            g_sq[t] = sq;
        }
    }
}

// -------- 4) main: 64 x 256 tiles, double-buffered rel preload,
//            8 chunks of 8 rows (rv[2][8] = 16 regs -> occupancy 6 blocks/SM) --------
__global__ void __launch_bounds__(TJ, 6) k_main(const float* __restrict__ rel) {
    const int n_tiles = g_meta[3];
    if ((int)blockIdx.x >= n_tiles) return;
    const int n_tj = g_meta[2];
    const int ti = blockIdx.x / n_tj;
    const int tj = blockIdx.x - ti * n_tj;
    const int iBase = ti * TI;
    const int jBase = tj * TJ;

    __shared__ float4 zi4[TI / 2][DD / 2];
    __shared__ float2 sqi[TI / 2];
    __shared__ float2 cip[TI / 2];
    __shared__ int    srow[TI];              // pre-shifted row offsets
    __shared__ float  red[8];

    const int tid = threadIdx.x;
    {
        int p = tid >> 3, d = tid & 7;
        int i0 = iBase + 2 * p;
        float2 pr = make_float2(g_z[(size_t)i0 * DD + d],
                                g_z[(size_t)(i0 + 1) * DD + d]);
        reinterpret_cast<float2*>(zi4)[p * DD + d] = pr;
    }
    if (tid < TI) srow[tid] = g_ucols[iBase + tid] << 14;   // *NN
    else if (tid < TI + 32) {
        int p = tid - TI;
        sqi[p] = make_float2(g_sq[iBase + 2 * p], g_sq[iBase + 2 * p + 1]);
    } else if (tid < TI + 64) {
        int p = tid - TI - 32;
        cip[p] = make_float2(g_cntf[iBase + 2 * p], g_cntf[iBase + 2 * p + 1]);
    }
    __syncthreads();

    const int j   = jBase + tid;
    const int col = g_ucols[j];
    const float cj = g_cntf[j];
    const float* relc = rel + col;

    // first rel chunk in flight before zj setup
    float rv[2][8];
#pragma unroll
    for (int k = 0; k < 8; k++)
        rv[0][k] = __ldg(relc + (size_t)srow[k]);

    float4 zj0 = *reinterpret_cast<const float4*>(g_z + (size_t)j * DD);
    float4 zj1 = *reinterpret_cast<const float4*>(g_z + (size_t)j * DD + 4);
    const float sqj = g_sq[j];

    unsigned long long zm[8];
    zm[0] = pk2(-2.f * zj0.x, -2.f * zj0.x);
    zm[1] = pk2(-2.f * zj0.y, -2.f * zj0.y);
    zm[2] = pk2(-2.f * zj0.z, -2.f * zj0.z);
    zm[3] = pk2(-2.f * zj0.w, -2.f * zj0.w);
    zm[4] = pk2(-2.f * zj1.x, -2.f * zj1.x);
    zm[5] = pk2(-2.f * zj1.y, -2.f * zj1.y);
    zm[6] = pk2(-2.f * zj1.z, -2.f * zj1.z);
    zm[7] = pk2(-2.f * zj1.w, -2.f * zj1.w);
    const unsigned long long sqj2 = pk2(sqj, sqj);

    float acc0 = 0.f, acc1 = 0.f;
#pragma unroll
    for (int c = 0; c < 8; c++) {
        const int cur = c & 1;
        if (c < 7) {                         // prefetch next 8-row chunk
#pragma unroll
            for (int k = 0; k < 8; k++)
                rv[cur ^ 1][k] = __ldg(relc + (size_t)srow[(c + 1) * 8 + k]);
        }
#pragma unroll
        for (int pp = 0; pp < 4; pp++) {
            const int p = c * 4 + pp;
            const ulonglong2* zp = reinterpret_cast<const ulonglong2*>(&zi4[p][0]);
            ulonglong2 e0 = zp[0];
            ulonglong2 e1 = zp[1];
            unsigned long long d2 =
                add2(*reinterpret_cast<const unsigned long long*>(&sqi[p]), sqj2);
            d2 = fma2(e0.x, zm[0], d2);
            d2 = fma2(e0.y, zm[1], d2);
            d2 = fma2(e1.x, zm[2], d2);
            d2 = fma2(e1.y, zm[3], d2);
            ulonglong2 e2 = zp[2];
            ulonglong2 e3 = zp[3];
            d2 = fma2(e2.x, zm[4], d2);
            d2 = fma2(e2.y, zm[5], d2);
            d2 = fma2(e3.x, zm[6], d2);
            d2 = fma2(e3.y, zm[7], d2);

            float d2a, d2b;
            upk2(d2, d2a, d2b);
            float2 ci = cip[p];
            {
                float r  = rv[cur][2 * pp];
                float dv = fsqrt_ap(fmaxf(d2a, 0.f));
                float t  = dv - r;
                acc0 = fmaf(ci.x, (t * t) * frcp_ap(r), acc0);
            }
            {
                float r  = rv[cur][2 * pp + 1];
                float dv = fsqrt_ap(fmaxf(d2b, 0.f));
                float t  = dv - r;
                acc1 = fmaf(ci.y, (t * t) * frcp_ap(r), acc1);
            }
        }
    }
    float acc = (acc0 + acc1) * cj;

#pragma unroll
    for (int o = 16; o > 0; o >>= 1)
        acc += __shfl_down_sync(0xFFFFFFFFu, acc, o);
    if ((tid & 31) == 0) red[tid >> 5] = acc;
    __syncthreads();
    if (tid < 8) {
        float v = red[tid];
#pragma unroll
        for (int o = 4; o > 0; o >>= 1)
            v += __shfl_down_sync(0xFFu, v, o);
        if (tid == 0) atomicAdd(&g_acc, (double)v);
    }
}

// -------- 5) finalize + restore accumulator --------
__global__ void k_final(float* __restrict__ out) {
    out[0] = (float)sqrt(g_acc);
    g_acc = 0.0;
}

extern "C" void kernel_launch(void* const* d_in, const int* in_sizes, int n_in,
                              void* d_out, int out_size) {
    const float* latent = (const float*)d_in[0];   // [N, D] fp32
    const float* relmat = (const float*)d_in[1];   // [N, N] fp32
    const int*   sidx   = (const int*)d_in[2];     // [S]   int32
    float* out = (float*)d_out;
    (void)in_sizes; (void)n_in; (void)out_size;

    k_hist<<<SS / 256, 256>>>(sidx, relmat);
    k_scan1<<<128, 128>>>();
    k_emit<<<128, 128>>>(latent);
    k_main<<<(SS / TI) * (SS / TJ), TJ>>>(relmat);
    k_final<<<1, 1>>>(out);
}